// round 3
// baseline (speedup 1.0000x reference)
#include <cuda_runtime.h>
#include <math.h>

#define SEQ 512   // hidden dim of h
#define EMB 512   // embedding dim
#define DD  384   // vfeat channels
#define LL  384   // vfeat regions

// Scratch (device globals — no allocation allowed in kernel_launch)
__device__ float g_ts[EMB * LL];     // tanh(s)             (512,384)
__device__ float g_z [LL * LL];      // wh @ tanh(s)        (384,384)
__device__ float g_alpha[LL * LL];   // softmax rows        (384,384)

// ---------------------------------------------------------------------------
// Register-tiled fp32 GEMM. 32x32 block tile, BK=32, 2x2 per thread,
// 256 threads/block. High block count -> full SM coverage.
//   FIRST=true :  g_ts = tanh( wv(512x384) @ v(384x384) + (wg@h)[m] )
//                 gh bias computed in-block (fused prologue).
//   FIRST=false:  g_z  = wh(384x512) @ g_ts(512x384)
// ---------------------------------------------------------------------------
template <int M, int N, int K, bool FIRST>
__global__ void __launch_bounds__(256) k_gemm(const float* __restrict__ A,
                                              const float* __restrict__ Bin,
                                              const float* __restrict__ wg,
                                              const float* __restrict__ h) {
    constexpr int BM = 32, BN = 32, BK = 32;
    __shared__ float As[BK][BM + 2];
    __shared__ float Bs[BK][BN + 2];
    __shared__ float sgh[BM];

    const float* __restrict__ B = FIRST ? Bin : (const float*)g_ts;

    int tx = threadIdx.x;          // 0..255
    int tn = tx & 15;              // 0..15  (n groups of 2)
    int tm = tx >> 4;              // 0..15  (m groups of 2)
    int bm = blockIdx.y;
    int bn = blockIdx.x;

    // Fused bias prologue: sgh[r] = sum_k wg[bm*32+r, k] * h[k]
    if (FIRST) {
        int r = tx >> 3, sub = tx & 7;           // 8 threads per row
        const float* wgr = wg + (bm * BM + r) * SEQ;
        float p = 0.f;
        #pragma unroll 8
        for (int k = sub; k < SEQ; k += 8) p += wgr[k] * h[k];
        p += __shfl_down_sync(0xffffffffu, p, 4);
        p += __shfl_down_sync(0xffffffffu, p, 2);
        p += __shfl_down_sync(0xffffffffu, p, 1);
        if (sub == 0) sgh[r] = p;
    }

    float a00 = 0.f, a01 = 0.f, a10 = 0.f, a11 = 0.f;

    for (int k0 = 0; k0 < K; k0 += BK) {
        __syncthreads();   // also covers sgh on first iteration
        #pragma unroll
        for (int i = 0; i < 4; i++) {
            int t = tx + i * 256;
            int m = t >> 5, k = t & 31;
            As[k][m] = A[(bm * BM + m) * K + k0 + k];
        }
        #pragma unroll
        for (int i = 0; i < 4; i++) {
            int t = tx + i * 256;
            int k = t >> 5, n = t & 31;
            Bs[k][n] = B[(k0 + k) * N + bn * BN + n];
        }
        __syncthreads();
        #pragma unroll
        for (int k = 0; k < BK; k++) {
            float2 ra = *(const float2*)&As[k][tm * 2];
            float2 rb = *(const float2*)&Bs[k][tn * 2];
            a00 += ra.x * rb.x; a01 += ra.x * rb.y;
            a10 += ra.y * rb.x; a11 += ra.y * rb.y;
        }
    }

    int m = bm * BM + tm * 2;
    int n = bn * BN + tn * 2;
    if (FIRST) {
        float b0 = sgh[tm * 2], b1 = sgh[tm * 2 + 1];
        g_ts[m * N + n]           = tanhf(a00 + b0);
        g_ts[m * N + n + 1]       = tanhf(a01 + b0);
        g_ts[(m + 1) * N + n]     = tanhf(a10 + b1);
        g_ts[(m + 1) * N + n + 1] = tanhf(a11 + b1);
    } else {
        g_z[m * N + n]           = a00;
        g_z[m * N + n + 1]       = a01;
        g_z[(m + 1) * N + n]     = a10;
        g_z[(m + 1) * N + n + 1] = a11;
    }
}

// ---------------------------------------------------------------------------
// Row softmax: one warp per row, float4 loads, shuffle-only reductions.
// ---------------------------------------------------------------------------
__global__ void k_softmax() {
    int warp = (blockIdx.x * blockDim.x + threadIdx.x) >> 5;   // 0..383
    int lane = threadIdx.x & 31;
    const float4* zr = (const float4*)(g_z + warp * LL);
    float4* ar = (float4*)(g_alpha + warp * LL);

    float4 x0 = zr[lane], x1 = zr[lane + 32], x2 = zr[lane + 64];

    float m = fmaxf(fmaxf(fmaxf(x0.x, x0.y), fmaxf(x0.z, x0.w)),
             fmaxf(fmaxf(fmaxf(x1.x, x1.y), fmaxf(x1.z, x1.w)),
                   fmaxf(fmaxf(x2.x, x2.y), fmaxf(x2.z, x2.w))));
    #pragma unroll
    for (int o = 16; o; o >>= 1) m = fmaxf(m, __shfl_xor_sync(0xffffffffu, m, o));

    x0.x = __expf(x0.x - m); x0.y = __expf(x0.y - m); x0.z = __expf(x0.z - m); x0.w = __expf(x0.w - m);
    x1.x = __expf(x1.x - m); x1.y = __expf(x1.y - m); x1.z = __expf(x1.z - m); x1.w = __expf(x1.w - m);
    x2.x = __expf(x2.x - m); x2.y = __expf(x2.y - m); x2.z = __expf(x2.z - m); x2.w = __expf(x2.w - m);

    float s = (x0.x + x0.y + x0.z + x0.w) + (x1.x + x1.y + x1.z + x1.w)
            + (x2.x + x2.y + x2.z + x2.w);
    #pragma unroll
    for (int o = 16; o; o >>= 1) s += __shfl_xor_sync(0xffffffffu, s, o);
    float inv = 1.f / s;

    x0.x *= inv; x0.y *= inv; x0.z *= inv; x0.w *= inv;
    x1.x *= inv; x1.y *= inv; x1.z *= inv; x1.w *= inv;
    x2.x *= inv; x2.y *= inv; x2.z *= inv; x2.w *= inv;
    ar[lane] = x0; ar[lane + 32] = x1; ar[lane + 64] = x2;
}

// ---------------------------------------------------------------------------
// out[i,j,k] = v[j,k] * alpha[i,j].
// Block = (j, chunk of 64 i's). 96 threads: thread t owns float4 #t of v row j
// IN REGISTERS (loaded once), alpha column slice staged in smem. Inner loop:
// LDS broadcast + 4 FMUL + 1 STG.128 streaming store. v read from L2 exactly
// 6x total (~7MB vs 221MB before) -> LTS bandwidth goes to the write stream.
// ---------------------------------------------------------------------------
__global__ void __launch_bounds__(96) k_out(const float* __restrict__ v,
                                            float4* __restrict__ out) {
    const int j  = blockIdx.x;    // 0..383
    const int ic = blockIdx.y;    // 0..5  (chunks of 64 rows i)
    const int t  = threadIdx.x;   // 0..95

    __shared__ float sa[64];

    float4 vv = ((const float4*)v)[j * (DD / 4) + t];
    if (t < 64) sa[t] = g_alpha[(ic * 64 + t) * LL + j];
    __syncthreads();

    // out float4 index for row i: (i*LL + j)*96 + t ; i-stride = LL*96
    float4* o = out + ((size_t)(ic * 64) * LL + j) * 96 + t;
    const int stride = LL * 96;

    #pragma unroll 4
    for (int ii = 0; ii < 64; ii++) {
        float a = sa[ii];
        float4 r;
        r.x = vv.x * a; r.y = vv.y * a; r.z = vv.z * a; r.w = vv.w * a;
        __stcs(o, r);
        o += stride;
    }
}

// ---------------------------------------------------------------------------
extern "C" void kernel_launch(void* const* d_in, const int* in_sizes, int n_in,
                              void* d_out, int out_size) {
    const float* h  = (const float*)d_in[0];   // (512,1)
    const float* v  = (const float*)d_in[1];   // (384,384)
    const float* wh = (const float*)d_in[2];   // (384,512)
    const float* wv = (const float*)d_in[3];   // (512,384)
    const float* wg = (const float*)d_in[4];   // (512,512)

    // ts = tanh(wv@v + wg@h)   (M=512, N=384, K=384), 192 blocks
    k_gemm<EMB, LL, DD, true><<<dim3(LL / 32, EMB / 32), 256>>>(wv, v, wg, h);

    // z = wh @ ts              (M=384, N=384, K=512), 144 blocks
    k_gemm<LL, LL, EMB, false><<<dim3(LL / 32, LL / 32), 256>>>(wh, nullptr, nullptr, nullptr);

    k_softmax<<<96, 128>>>();

    // out: 2304 blocks x 96 threads
    k_out<<<dim3(LL, 6), 96>>>(v, (float4*)d_out);
    (void)in_sizes; (void)n_in; (void)out_size;
}

// round 4
// speedup vs baseline: 1.0004x; 1.0004x over previous
#include <cuda_runtime.h>
#include <math.h>

#define SEQ 512   // hidden dim of h
#define EMB 512   // embedding dim
#define DD  384   // vfeat channels
#define LL  384   // vfeat regions

// Scratch (device globals — no allocation allowed in kernel_launch)
__device__ float g_ts[EMB * LL];     // tanh(s)             (512,384)
__device__ float g_z [LL * LL];      // wh @ tanh(s)        (384,384)
__device__ float g_alpha[LL * LL];   // softmax rows        (384,384)

// ---------------------------------------------------------------------------
// Register-tiled fp32 GEMM. 32x32 block tile, BK=32, 2x2 per thread,
// 256 threads/block.
//   FIRST=true :  g_ts = tanh( wv(512x384) @ v(384x384) + (wg@h)[m] )
//   FIRST=false:  g_z  = wh(384x512) @ g_ts(512x384)
// ---------------------------------------------------------------------------
template <int M, int N, int K, bool FIRST>
__global__ void __launch_bounds__(256) k_gemm(const float* __restrict__ A,
                                              const float* __restrict__ Bin,
                                              const float* __restrict__ wg,
                                              const float* __restrict__ h) {
    constexpr int BM = 32, BN = 32, BK = 32;
    __shared__ float As[BK][BM + 2];
    __shared__ float Bs[BK][BN + 2];
    __shared__ float sgh[BM];

    const float* __restrict__ B = FIRST ? Bin : (const float*)g_ts;

    int tx = threadIdx.x;          // 0..255
    int tn = tx & 15;              // 0..15  (n groups of 2)
    int tm = tx >> 4;              // 0..15  (m groups of 2)
    int bm = blockIdx.y;
    int bn = blockIdx.x;

    if (FIRST) {
        int r = tx >> 3, sub = tx & 7;           // 8 threads per row
        const float* wgr = wg + (bm * BM + r) * SEQ;
        float p = 0.f;
        #pragma unroll 8
        for (int k = sub; k < SEQ; k += 8) p += wgr[k] * h[k];
        p += __shfl_down_sync(0xffffffffu, p, 4);
        p += __shfl_down_sync(0xffffffffu, p, 2);
        p += __shfl_down_sync(0xffffffffu, p, 1);
        if (sub == 0) sgh[r] = p;
    }

    float a00 = 0.f, a01 = 0.f, a10 = 0.f, a11 = 0.f;

    for (int k0 = 0; k0 < K; k0 += BK) {
        __syncthreads();   // also covers sgh on first iteration
        #pragma unroll
        for (int i = 0; i < 4; i++) {
            int t = tx + i * 256;
            int m = t >> 5, k = t & 31;
            As[k][m] = A[(bm * BM + m) * K + k0 + k];
        }
        #pragma unroll
        for (int i = 0; i < 4; i++) {
            int t = tx + i * 256;
            int k = t >> 5, n = t & 31;
            Bs[k][n] = B[(k0 + k) * N + bn * BN + n];
        }
        __syncthreads();
        #pragma unroll
        for (int k = 0; k < BK; k++) {
            float2 ra = *(const float2*)&As[k][tm * 2];
            float2 rb = *(const float2*)&Bs[k][tn * 2];
            a00 += ra.x * rb.x; a01 += ra.x * rb.y;
            a10 += ra.y * rb.x; a11 += ra.y * rb.y;
        }
    }

    int m = bm * BM + tm * 2;
    int n = bn * BN + tn * 2;
    if (FIRST) {
        float b0 = sgh[tm * 2], b1 = sgh[tm * 2 + 1];
        g_ts[m * N + n]           = tanhf(a00 + b0);
        g_ts[m * N + n + 1]       = tanhf(a01 + b0);
        g_ts[(m + 1) * N + n]     = tanhf(a10 + b1);
        g_ts[(m + 1) * N + n + 1] = tanhf(a11 + b1);
    } else {
        g_z[m * N + n]           = a00;
        g_z[m * N + n + 1]       = a01;
        g_z[(m + 1) * N + n]     = a10;
        g_z[(m + 1) * N + n + 1] = a11;
    }
}

// ---------------------------------------------------------------------------
// Row softmax: one warp per row, float4 loads, shuffle-only reductions.
// ---------------------------------------------------------------------------
__global__ void k_softmax() {
    int warp = (blockIdx.x * blockDim.x + threadIdx.x) >> 5;   // 0..383
    int lane = threadIdx.x & 31;
    const float4* zr = (const float4*)(g_z + warp * LL);
    float4* ar = (float4*)(g_alpha + warp * LL);

    float4 x0 = zr[lane], x1 = zr[lane + 32], x2 = zr[lane + 64];

    float m = fmaxf(fmaxf(fmaxf(x0.x, x0.y), fmaxf(x0.z, x0.w)),
             fmaxf(fmaxf(fmaxf(x1.x, x1.y), fmaxf(x1.z, x1.w)),
                   fmaxf(fmaxf(x2.x, x2.y), fmaxf(x2.z, x2.w))));
    #pragma unroll
    for (int o = 16; o; o >>= 1) m = fmaxf(m, __shfl_xor_sync(0xffffffffu, m, o));

    x0.x = __expf(x0.x - m); x0.y = __expf(x0.y - m); x0.z = __expf(x0.z - m); x0.w = __expf(x0.w - m);
    x1.x = __expf(x1.x - m); x1.y = __expf(x1.y - m); x1.z = __expf(x1.z - m); x1.w = __expf(x1.w - m);
    x2.x = __expf(x2.x - m); x2.y = __expf(x2.y - m); x2.z = __expf(x2.z - m); x2.w = __expf(x2.w - m);

    float s = (x0.x + x0.y + x0.z + x0.w) + (x1.x + x1.y + x1.z + x1.w)
            + (x2.x + x2.y + x2.z + x2.w);
    #pragma unroll
    for (int o = 16; o; o >>= 1) s += __shfl_xor_sync(0xffffffffu, s, o);
    float inv = 1.f / s;

    x0.x *= inv; x0.y *= inv; x0.z *= inv; x0.w *= inv;
    x1.x *= inv; x1.y *= inv; x1.z *= inv; x1.w *= inv;
    x2.x *= inv; x2.y *= inv; x2.z *= inv; x2.w *= inv;
    ar[lane] = x0; ar[lane + 32] = x1; ar[lane + 64] = x2;
}

// ---------------------------------------------------------------------------
// out[i,j,k] = v[j,k] * alpha[i,j].
// Block = (32-j tile, 16-i chunk), 384 threads. Thread owns fixed (g,k4):
// g = t/96 in 0..3, k4 = t%96. It keeps v[jb*32 + jlo*4 + g][k4] for
// jlo=0..7 in 8 float4 REGISTERS. alpha tile (16x32) in smem.
// Per i, the block writes one fully CONTIGUOUS 48KB burst; the 12 jb-blocks
// tile each 576KB i-row exactly. Grid 288 blocks -> ~2 blocks/SM, 24 warps.
// ---------------------------------------------------------------------------
__global__ void __launch_bounds__(384) k_out(const float* __restrict__ v,
                                             float4* __restrict__ out) {
    const int jb = blockIdx.x;    // 0..11   (32 j's each)
    const int ic = blockIdx.y;    // 0..23   (16 i's each)
    const int t  = threadIdx.x;   // 0..383

    const int g  = t / 96;        // 0..3   (computed once)
    const int k4 = t % 96;        // 0..95

    __shared__ float sa[16][32];

    // v rows for this thread: j = jb*32 + jlo*4 + g, element k4 (float4)
    float4 vv[8];
    #pragma unroll
    for (int jlo = 0; jlo < 8; jlo++)
        vv[jlo] = ((const float4*)v)[(jb * 32 + jlo * 4 + g) * 96 + k4];

    // alpha tile: rows ic*16..+15, cols jb*32..+31
    #pragma unroll
    for (int idx = t; idx < 512; idx += 384) {
        int r = idx >> 5, c = idx & 31;
        sa[r][c] = g_alpha[(ic * 16 + r) * LL + jb * 32 + c];
    }
    __syncthreads();

    #pragma unroll 2
    for (int il = 0; il < 16; il++) {
        // base of this block's contiguous 48KB region for row i (float4 units)
        float4* o = out + ((size_t)(ic * 16 + il) * LL + jb * 32) * 96 + g * 96 + k4;
        #pragma unroll
        for (int jlo = 0; jlo < 8; jlo++) {
            float a = sa[il][jlo * 4 + g];
            float4 r;
            r.x = vv[jlo].x * a; r.y = vv[jlo].y * a;
            r.z = vv[jlo].z * a; r.w = vv[jlo].w * a;
            __stcs(o + jlo * 4 * 96, r);
        }
    }
}

// ---------------------------------------------------------------------------
extern "C" void kernel_launch(void* const* d_in, const int* in_sizes, int n_in,
                              void* d_out, int out_size) {
    const float* h  = (const float*)d_in[0];   // (512,1)
    const float* v  = (const float*)d_in[1];   // (384,384)
    const float* wh = (const float*)d_in[2];   // (384,512)
    const float* wv = (const float*)d_in[3];   // (512,384)
    const float* wg = (const float*)d_in[4];   // (512,512)

    // ts = tanh(wv@v + wg@h)   (M=512, N=384, K=384), 192 blocks
    k_gemm<EMB, LL, DD, true><<<dim3(LL / 32, EMB / 32), 256>>>(wv, v, wg, h);

    // z = wh @ ts              (M=384, N=384, K=512), 144 blocks
    k_gemm<LL, LL, EMB, false><<<dim3(LL / 32, LL / 32), 256>>>(wh, nullptr, nullptr, nullptr);

    k_softmax<<<96, 128>>>();

    // out: (12 j-tiles) x (24 i-chunks) = 288 blocks x 384 threads
    k_out<<<dim3(12, 24), 384>>>(v, (float4*)d_out);
    (void)in_sizes; (void)n_in; (void)out_size;
}

// round 5
// speedup vs baseline: 1.1599x; 1.1594x over previous
#include <cuda_runtime.h>
#include <math.h>

#define SEQ 512   // hidden dim of h
#define EMB 512   // embedding dim
#define DD  384   // vfeat channels
#define LL  384   // vfeat regions

// Scratch (device globals — no allocation allowed in kernel_launch)
__device__ float g_spart[4][EMB * LL];   // split-K partials of s = wv@v (+bias in part 0)
__device__ float g_zpart[4][LL * LL];    // split-K partials of z = wh@tanh(s)
__device__ float g_alpha[LL * LL];       // softmax rows (384,384)

// ---------------------------------------------------------------------------
// GEMM1 split-K: g_spart[kc] = wv[:, kc*96:(kc+1)*96] @ v[kc*96:(kc+1)*96, :]
// 64x64 block tile, BK=16, 4x4 per thread, 256 threads.
// kc==0 blocks also fold in the bias gh[m] = (wg@h)[m].
// Grid: (6 n-tiles, 8 m-tiles, 4 kc) = 192 blocks.
// ---------------------------------------------------------------------------
__global__ void __launch_bounds__(256) k_gemm1(const float* __restrict__ wv,
                                               const float* __restrict__ v,
                                               const float* __restrict__ wg,
                                               const float* __restrict__ h) {
    constexpr int BK = 16, KC = 96;
    __shared__ float As[BK][68];   // As[k][m], row stride 68*4B = 272B (16B-aligned)
    __shared__ float Bs[BK][68];
    __shared__ float sgh[64];

    const int tx = threadIdx.x;
    const int tn = tx & 15;        // 0..15  (n groups of 4)
    const int tm = tx >> 4;        // 0..15  (m groups of 4)
    const int bn = blockIdx.x, bm = blockIdx.y, kc = blockIdx.z;

    // bias prologue (kc==0 only): sgh[r] = sum_k wg[bm*64+r, k] * h[k]
    if (kc == 0) {
        int r = tx >> 2, sub = tx & 3;            // 4 threads per row
        const float* wgr = wg + (bm * 64 + r) * SEQ;
        float p = 0.f;
        #pragma unroll 8
        for (int k = sub; k < SEQ; k += 4) p += wgr[k] * h[k];
        p += __shfl_down_sync(0xffffffffu, p, 2);
        p += __shfl_down_sync(0xffffffffu, p, 1);
        if (sub == 0) sgh[r] = p;
    }

    float acc[4][4] = {};

    const int kbase = kc * KC;
    for (int k0 = 0; k0 < KC; k0 += BK) {
        __syncthreads();
        // A tile: wv rows bm*64..+63, cols kbase+k0..+15. float4 along K.
        {
            int m = tx >> 2, kq = (tx & 3) * 4;
            float4 a = *(const float4*)&wv[(bm * 64 + m) * DD + kbase + k0 + kq];
            As[kq + 0][m] = a.x; As[kq + 1][m] = a.y;
            As[kq + 2][m] = a.z; As[kq + 3][m] = a.w;
        }
        // B tile: v rows kbase+k0..+15, cols bn*64..+63. float4 along N.
        {
            int k = tx >> 4, nq = (tx & 15) * 4;
            float4 b = *(const float4*)&v[(kbase + k0 + k) * LL + bn * 64 + nq];
            *(float4*)&Bs[k][nq] = b;
        }
        __syncthreads();
        #pragma unroll
        for (int k = 0; k < BK; k++) {
            float4 ra = *(const float4*)&As[k][tm * 4];
            float4 rb = *(const float4*)&Bs[k][tn * 4];
            float a_[4] = {ra.x, ra.y, ra.z, ra.w};
            float b_[4] = {rb.x, rb.y, rb.z, rb.w};
            #pragma unroll
            for (int i = 0; i < 4; i++)
                #pragma unroll
                for (int j = 0; j < 4; j++)
                    acc[i][j] += a_[i] * b_[j];
        }
    }
    __syncthreads();   // sgh visible (kc==0); harmless otherwise

    float* outp = g_spart[kc];
    #pragma unroll
    for (int i = 0; i < 4; i++) {
        int m = bm * 64 + tm * 4 + i;
        float bias = (kc == 0) ? sgh[tm * 4 + i] : 0.f;
        float4 r;
        r.x = acc[i][0] + bias; r.y = acc[i][1] + bias;
        r.z = acc[i][2] + bias; r.w = acc[i][3] + bias;
        *(float4*)&outp[m * LL + bn * 64 + tn * 4] = r;
    }
}

// ---------------------------------------------------------------------------
// GEMM2 split-K: g_zpart[kc] = wh[:, kc*128:+128] @ tanh(s)[kc*128:+128, :]
// B element built on the fly: tanh(p0+p1+p2+p3).
// Grid: (6, 6, 4) = 144 blocks.
// ---------------------------------------------------------------------------
__global__ void __launch_bounds__(256) k_gemm2(const float* __restrict__ wh) {
    constexpr int BK = 16, KC = 128;
    __shared__ float As[BK][68];
    __shared__ float Bs[BK][68];

    const int tx = threadIdx.x;
    const int tn = tx & 15;
    const int tm = tx >> 4;
    const int bn = blockIdx.x, bm = blockIdx.y, kc = blockIdx.z;

    float acc[4][4] = {};

    const int kbase = kc * KC;
    for (int k0 = 0; k0 < KC; k0 += BK) {
        __syncthreads();
        // A tile: wh rows bm*64..+63, cols kbase+k0..+15
        {
            int m = tx >> 2, kq = (tx & 3) * 4;
            float4 a = *(const float4*)&wh[(bm * 64 + m) * EMB + kbase + k0 + kq];
            As[kq + 0][m] = a.x; As[kq + 1][m] = a.y;
            As[kq + 2][m] = a.z; As[kq + 3][m] = a.w;
        }
        // B tile: ts rows kbase+k0..+15, cols bn*64..+63, built as tanh(sum parts)
        {
            int k = tx >> 4, nq = (tx & 15) * 4;
            int off = (kbase + k0 + k) * LL + bn * 64 + nq;
            float4 p0 = *(const float4*)&g_spart[0][off];
            float4 p1 = *(const float4*)&g_spart[1][off];
            float4 p2 = *(const float4*)&g_spart[2][off];
            float4 p3 = *(const float4*)&g_spart[3][off];
            float4 b;
            b.x = tanhf(p0.x + p1.x + p2.x + p3.x);
            b.y = tanhf(p0.y + p1.y + p2.y + p3.y);
            b.z = tanhf(p0.z + p1.z + p2.z + p3.z);
            b.w = tanhf(p0.w + p1.w + p2.w + p3.w);
            *(float4*)&Bs[k][nq] = b;
        }
        __syncthreads();
        #pragma unroll
        for (int k = 0; k < BK; k++) {
            float4 ra = *(const float4*)&As[k][tm * 4];
            float4 rb = *(const float4*)&Bs[k][tn * 4];
            float a_[4] = {ra.x, ra.y, ra.z, ra.w};
            float b_[4] = {rb.x, rb.y, rb.z, rb.w};
            #pragma unroll
            for (int i = 0; i < 4; i++)
                #pragma unroll
                for (int j = 0; j < 4; j++)
                    acc[i][j] += a_[i] * b_[j];
        }
    }

    float* outp = g_zpart[kc];
    #pragma unroll
    for (int i = 0; i < 4; i++) {
        int m = bm * 64 + tm * 4 + i;
        float4 r;
        r.x = acc[i][0]; r.y = acc[i][1]; r.z = acc[i][2]; r.w = acc[i][3];
        *(float4*)&outp[m * LL + bn * 64 + tn * 4] = r;
    }
}

// ---------------------------------------------------------------------------
// Row softmax over z = sum of 4 partials. One warp per row, float4 loads.
// ---------------------------------------------------------------------------
__global__ void k_softmax() {
    int warp = (blockIdx.x * blockDim.x + threadIdx.x) >> 5;   // 0..383
    int lane = threadIdx.x & 31;
    const int row = warp * LL;
    float4* ar = (float4*)(g_alpha + row);

    float4 x[3];
    #pragma unroll
    for (int c = 0; c < 3; c++) {
        int idx = (row >> 2) + lane + c * 32;
        float4 p0 = ((const float4*)g_zpart[0])[idx];
        float4 p1 = ((const float4*)g_zpart[1])[idx];
        float4 p2 = ((const float4*)g_zpart[2])[idx];
        float4 p3 = ((const float4*)g_zpart[3])[idx];
        x[c].x = p0.x + p1.x + p2.x + p3.x;
        x[c].y = p0.y + p1.y + p2.y + p3.y;
        x[c].z = p0.z + p1.z + p2.z + p3.z;
        x[c].w = p0.w + p1.w + p2.w + p3.w;
    }

    float m = -1e30f;
    #pragma unroll
    for (int c = 0; c < 3; c++)
        m = fmaxf(m, fmaxf(fmaxf(x[c].x, x[c].y), fmaxf(x[c].z, x[c].w)));
    #pragma unroll
    for (int o = 16; o; o >>= 1) m = fmaxf(m, __shfl_xor_sync(0xffffffffu, m, o));

    float s = 0.f;
    #pragma unroll
    for (int c = 0; c < 3; c++) {
        x[c].x = __expf(x[c].x - m); x[c].y = __expf(x[c].y - m);
        x[c].z = __expf(x[c].z - m); x[c].w = __expf(x[c].w - m);
        s += (x[c].x + x[c].y) + (x[c].z + x[c].w);
    }
    #pragma unroll
    for (int o = 16; o; o >>= 1) s += __shfl_xor_sync(0xffffffffu, s, o);
    float inv = 1.f / s;

    #pragma unroll
    for (int c = 0; c < 3; c++) {
        x[c].x *= inv; x[c].y *= inv; x[c].z *= inv; x[c].w *= inv;
        ar[lane + c * 32] = x[c];
    }
}

// ---------------------------------------------------------------------------
// out[i,j,k] = v[j,k] * alpha[i,j].  v rows in registers, alpha tile in smem,
// contiguous 48KB bursts per i. (At write roofline — unchanged from R4.)
// ---------------------------------------------------------------------------
__global__ void __launch_bounds__(384) k_out(const float* __restrict__ v,
                                             float4* __restrict__ out) {
    const int jb = blockIdx.x;    // 0..11   (32 j's each)
    const int ic = blockIdx.y;    // 0..23   (16 i's each)
    const int t  = threadIdx.x;   // 0..383

    const int g  = t / 96;        // 0..3
    const int k4 = t % 96;        // 0..95

    __shared__ float sa[16][32];

    float4 vv[8];
    #pragma unroll
    for (int jlo = 0; jlo < 8; jlo++)
        vv[jlo] = ((const float4*)v)[(jb * 32 + jlo * 4 + g) * 96 + k4];

    #pragma unroll
    for (int idx = t; idx < 512; idx += 384) {
        int r = idx >> 5, c = idx & 31;
        sa[r][c] = g_alpha[(ic * 16 + r) * LL + jb * 32 + c];
    }
    __syncthreads();

    #pragma unroll 2
    for (int il = 0; il < 16; il++) {
        float4* o = out + ((size_t)(ic * 16 + il) * LL + jb * 32) * 96 + g * 96 + k4;
        #pragma unroll
        for (int jlo = 0; jlo < 8; jlo++) {
            float a = sa[il][jlo * 4 + g];
            float4 r;
            r.x = vv[jlo].x * a; r.y = vv[jlo].y * a;
            r.z = vv[jlo].z * a; r.w = vv[jlo].w * a;
            __stcs(o + jlo * 4 * 96, r);
        }
    }
}

// ---------------------------------------------------------------------------
extern "C" void kernel_launch(void* const* d_in, const int* in_sizes, int n_in,
                              void* d_out, int out_size) {
    const float* h  = (const float*)d_in[0];   // (512,1)
    const float* v  = (const float*)d_in[1];   // (384,384)
    const float* wh = (const float*)d_in[2];   // (384,512)
    const float* wv = (const float*)d_in[3];   // (512,384)
    const float* wg = (const float*)d_in[4];   // (512,512)

    // s partials (+bias in part0): 192 blocks
    k_gemm1<<<dim3(LL / 64, EMB / 64, 4), 256>>>(wv, v, wg, h);

    // z partials (tanh+sum fused into B load): 144 blocks
    k_gemm2<<<dim3(LL / 64, LL / 64, 4), 256>>>(wh);

    k_softmax<<<96, 128>>>();

    k_out<<<dim3(12, 24), 384>>>(v, (float4*)d_out);
    (void)in_sizes; (void)n_in; (void)out_size;
}

// round 6
// speedup vs baseline: 1.2063x; 1.0400x over previous
#include <cuda_runtime.h>
#include <math.h>

#define SEQ 512   // hidden dim of h
#define EMB 512   // embedding dim
#define DD  384   // vfeat channels
#define LL  384   // vfeat regions

// Scratch (device globals — no allocation allowed in kernel_launch)
__device__ float g_spart[6][EMB * LL];   // split-K partials of s = wv@v (+bias in part 0)
__device__ float g_zpart[8][LL * LL];    // split-K partials of z = wh@tanh(s)
__device__ float g_alpha[LL * LL];       // softmax rows (384,384)

// ---------------------------------------------------------------------------
// GEMM1 split-K6: g_spart[kc] = wv[:, kc*64:+64] @ v[kc*64:+64, :]
// 64x64 block tile, WHOLE 64-deep K-slice staged in smem (one sync pair),
// 4x4 per thread, 256 threads. kc==0 also folds in bias gh[m] = (wg@h)[m].
// Grid: (6 n, 8 m, 6 kc) = 288 blocks (~2/SM, one wave).
// ---------------------------------------------------------------------------
__global__ void __launch_bounds__(256) k_gemm1(const float* __restrict__ wv,
                                               const float* __restrict__ v,
                                               const float* __restrict__ wg,
                                               const float* __restrict__ h) {
    constexpr int KC = 64;
    __shared__ float As[KC][68];   // As[k][m]; row stride 272B keeps float4 alignment
    __shared__ float Bs[KC][68];
    __shared__ float sgh[64];

    const int tx = threadIdx.x;
    const int tn = tx & 15;        // n groups of 4
    const int tm = tx >> 4;        // m groups of 4
    const int bn = blockIdx.x, bm = blockIdx.y, kc = blockIdx.z;
    const int kbase = kc * KC;

    // bias prologue (kc==0 only): sgh[r] = sum_k wg[bm*64+r, k] * h[k]
    if (kc == 0) {
        int r = tx >> 2, sub = tx & 3;            // 4 threads per row
        const float* wgr = wg + (bm * 64 + r) * SEQ;
        float p = 0.f;
        #pragma unroll 8
        for (int k = sub; k < SEQ; k += 4) p += wgr[k] * h[k];
        p += __shfl_down_sync(0xffffffffu, p, 2);
        p += __shfl_down_sync(0xffffffffu, p, 1);
        if (sub == 0) sgh[r] = p;
    }

    // A tile: wv rows bm*64..+63, cols kbase..+63 -> transposed As[k][m]
    {
        int m = tx >> 2, c0 = (tx & 3) * 16;
        const float* ap = &wv[(bm * 64 + m) * DD + kbase + c0];
        #pragma unroll
        for (int q = 0; q < 4; q++) {
            float4 a = *(const float4*)(ap + 4 * q);
            As[c0 + 4 * q + 0][m] = a.x; As[c0 + 4 * q + 1][m] = a.y;
            As[c0 + 4 * q + 2][m] = a.z; As[c0 + 4 * q + 3][m] = a.w;
        }
    }
    // B tile: v rows kbase..+63, cols bn*64..+63
    #pragma unroll
    for (int q = 0; q < 4; q++) {
        int e = tx + 256 * q;
        int k = e >> 4, n4 = (e & 15) * 4;
        *(float4*)&Bs[k][n4] = *(const float4*)&v[(kbase + k) * LL + bn * 64 + n4];
    }
    __syncthreads();   // also publishes sgh

    float acc[4][4] = {};
    #pragma unroll 8
    for (int k = 0; k < KC; k++) {
        float4 ra = *(const float4*)&As[k][tm * 4];
        float4 rb = *(const float4*)&Bs[k][tn * 4];
        float a_[4] = {ra.x, ra.y, ra.z, ra.w};
        float b_[4] = {rb.x, rb.y, rb.z, rb.w};
        #pragma unroll
        for (int i = 0; i < 4; i++)
            #pragma unroll
            for (int j = 0; j < 4; j++)
                acc[i][j] += a_[i] * b_[j];
    }

    float* outp = g_spart[kc];
    #pragma unroll
    for (int i = 0; i < 4; i++) {
        int m = bm * 64 + tm * 4 + i;
        float bias = (kc == 0) ? sgh[tm * 4 + i] : 0.f;
        float4 r;
        r.x = acc[i][0] + bias; r.y = acc[i][1] + bias;
        r.z = acc[i][2] + bias; r.w = acc[i][3] + bias;
        *(float4*)&outp[m * LL + bn * 64 + tn * 4] = r;
    }
}

// ---------------------------------------------------------------------------
// GEMM2 split-K8: g_zpart[kc] = wh[:, kc*64:+64] @ tanh(s)[kc*64:+64, :]
// B element built on the fly: tanh(sum of 6 s-partials). One sync pair.
// Grid: (6, 6, 8) = 288 blocks.
// ---------------------------------------------------------------------------
__global__ void __launch_bounds__(256) k_gemm2(const float* __restrict__ wh) {
    constexpr int KC = 64;
    __shared__ float As[KC][68];
    __shared__ float Bs[KC][68];

    const int tx = threadIdx.x;
    const int tn = tx & 15;
    const int tm = tx >> 4;
    const int bn = blockIdx.x, bm = blockIdx.y, kc = blockIdx.z;
    const int kbase = kc * KC;

    // A tile: wh rows bm*64..+63, cols kbase..+63 -> As[k][m]
    {
        int m = tx >> 2, c0 = (tx & 3) * 16;
        const float* ap = &wh[(bm * 64 + m) * EMB + kbase + c0];
        #pragma unroll
        for (int q = 0; q < 4; q++) {
            float4 a = *(const float4*)(ap + 4 * q);
            As[c0 + 4 * q + 0][m] = a.x; As[c0 + 4 * q + 1][m] = a.y;
            As[c0 + 4 * q + 2][m] = a.z; As[c0 + 4 * q + 3][m] = a.w;
        }
    }
    // B tile: ts rows kbase..+63, cols bn*64..+63 = tanh(sum of 6 partials)
    #pragma unroll
    for (int q = 0; q < 4; q++) {
        int e = tx + 256 * q;
        int k = e >> 4, n4 = (e & 15) * 4;
        int off = (kbase + k) * LL + bn * 64 + n4;
        float4 s = *(const float4*)&g_spart[0][off];
        #pragma unroll
        for (int p = 1; p < 6; p++) {
            float4 t = *(const float4*)&g_spart[p][off];
            s.x += t.x; s.y += t.y; s.z += t.z; s.w += t.w;
        }
        float4 b;
        b.x = tanhf(s.x); b.y = tanhf(s.y); b.z = tanhf(s.z); b.w = tanhf(s.w);
        *(float4*)&Bs[k][n4] = b;
    }
    __syncthreads();

    float acc[4][4] = {};
    #pragma unroll 8
    for (int k = 0; k < KC; k++) {
        float4 ra = *(const float4*)&As[k][tm * 4];
        float4 rb = *(const float4*)&Bs[k][tn * 4];
        float a_[4] = {ra.x, ra.y, ra.z, ra.w};
        float b_[4] = {rb.x, rb.y, rb.z, rb.w};
        #pragma unroll
        for (int i = 0; i < 4; i++)
            #pragma unroll
            for (int j = 0; j < 4; j++)
                acc[i][j] += a_[i] * b_[j];
    }

    float* outp = g_zpart[kc];
    #pragma unroll
    for (int i = 0; i < 4; i++) {
        int m = bm * 64 + tm * 4 + i;
        float4 r;
        r.x = acc[i][0]; r.y = acc[i][1]; r.z = acc[i][2]; r.w = acc[i][3];
        *(float4*)&outp[m * LL + bn * 64 + tn * 4] = r;
    }
}

// ---------------------------------------------------------------------------
// Row softmax over z = sum of 8 partials. One warp per row, float4 loads.
// ---------------------------------------------------------------------------
__global__ void k_softmax() {
    int warp = (blockIdx.x * blockDim.x + threadIdx.x) >> 5;   // 0..383
    int lane = threadIdx.x & 31;
    const int row = warp * LL;
    float4* ar = (float4*)(g_alpha + row);

    float4 x[3];
    #pragma unroll
    for (int c = 0; c < 3; c++) {
        int idx = (row >> 2) + lane + c * 32;
        float4 s = ((const float4*)g_zpart[0])[idx];
        #pragma unroll
        for (int p = 1; p < 8; p++) {
            float4 t = ((const float4*)g_zpart[p])[idx];
            s.x += t.x; s.y += t.y; s.z += t.z; s.w += t.w;
        }
        x[c] = s;
    }

    float m = -1e30f;
    #pragma unroll
    for (int c = 0; c < 3; c++)
        m = fmaxf(m, fmaxf(fmaxf(x[c].x, x[c].y), fmaxf(x[c].z, x[c].w)));
    #pragma unroll
    for (int o = 16; o; o >>= 1) m = fmaxf(m, __shfl_xor_sync(0xffffffffu, m, o));

    float s = 0.f;
    #pragma unroll
    for (int c = 0; c < 3; c++) {
        x[c].x = __expf(x[c].x - m); x[c].y = __expf(x[c].y - m);
        x[c].z = __expf(x[c].z - m); x[c].w = __expf(x[c].w - m);
        s += (x[c].x + x[c].y) + (x[c].z + x[c].w);
    }
    #pragma unroll
    for (int o = 16; o; o >>= 1) s += __shfl_xor_sync(0xffffffffu, s, o);
    float inv = 1.f / s;

    #pragma unroll
    for (int c = 0; c < 3; c++) {
        x[c].x *= inv; x[c].y *= inv; x[c].z *= inv; x[c].w *= inv;
        ar[lane + c * 32] = x[c];
    }
}

// ---------------------------------------------------------------------------
// out[i,j,k] = v[j,k] * alpha[i,j].  v rows in registers, alpha tile in smem,
// contiguous 48KB bursts per i. At write roofline (6.1 TB/s) — unchanged.
// ---------------------------------------------------------------------------
__global__ void __launch_bounds__(384) k_out(const float* __restrict__ v,
                                             float4* __restrict__ out) {
    const int jb = blockIdx.x;    // 0..11   (32 j's each)
    const int ic = blockIdx.y;    // 0..23   (16 i's each)
    const int t  = threadIdx.x;   // 0..383

    const int g  = t / 96;        // 0..3
    const int k4 = t % 96;        // 0..95

    __shared__ float sa[16][32];

    float4 vv[8];
    #pragma unroll
    for (int jlo = 0; jlo < 8; jlo++)
        vv[jlo] = ((const float4*)v)[(jb * 32 + jlo * 4 + g) * 96 + k4];

    #pragma unroll
    for (int idx = t; idx < 512; idx += 384) {
        int r = idx >> 5, c = idx & 31;
        sa[r][c] = g_alpha[(ic * 16 + r) * LL + jb * 32 + c];
    }
    __syncthreads();

    #pragma unroll 2
    for (int il = 0; il < 16; il++) {
        float4* o = out + ((size_t)(ic * 16 + il) * LL + jb * 32) * 96 + g * 96 + k4;
        #pragma unroll
        for (int jlo = 0; jlo < 8; jlo++) {
            float a = sa[il][jlo * 4 + g];
            float4 r;
            r.x = vv[jlo].x * a; r.y = vv[jlo].y * a;
            r.z = vv[jlo].z * a; r.w = vv[jlo].w * a;
            __stcs(o + jlo * 4 * 96, r);
        }
    }
}

// ---------------------------------------------------------------------------
extern "C" void kernel_launch(void* const* d_in, const int* in_sizes, int n_in,
                              void* d_out, int out_size) {
    const float* h  = (const float*)d_in[0];   // (512,1)
    const float* v  = (const float*)d_in[1];   // (384,384)
    const float* wh = (const float*)d_in[2];   // (384,512)
    const float* wv = (const float*)d_in[3];   // (512,384)
    const float* wg = (const float*)d_in[4];   // (512,512)

    // s partials (+bias in part0): (6,8,6) = 288 blocks
    k_gemm1<<<dim3(LL / 64, EMB / 64, 6), 256>>>(wv, v, wg, h);

    // z partials (tanh + 6-partial sum fused into B load): (6,6,8) = 288 blocks
    k_gemm2<<<dim3(LL / 64, LL / 64, 8), 256>>>(wh);

    k_softmax<<<96, 128>>>();

    k_out<<<dim3(12, 24), 384>>>(v, (float4*)d_out);
    (void)in_sizes; (void)n_in; (void)out_size;
}

// round 7
// speedup vs baseline: 1.3091x; 1.0852x over previous
#include <cuda_runtime.h>
#include <math.h>

#define SEQ 512   // hidden dim of h
#define EMB 512   // embedding dim
#define DD  384   // vfeat channels
#define LL  384   // vfeat regions

#define NP1 12    // split-K partials for GEMM1 (K=384, slab 32)
#define NP2 16    // split-K partials for GEMM2 (K=512, slab 32)

// Scratch (device globals — no allocation allowed in kernel_launch)
__device__ float g_gh[EMB];               // wg @ h
__device__ float g_spart[NP1][EMB * LL];  // split-K partials of s = wv@v (+bias in part 0)
__device__ float g_zpart[NP2][LL * LL];   // split-K partials of z = wh@tanh(s)
__device__ float g_alpha[LL * LL];        // softmax rows (384,384)

// ---------------------------------------------------------------------------
// gh[row] = dot(wg[row,:], h). One warp per row; 64 blocks x 256 threads.
// Fully overlapped under GEMM1 via PDL.
// ---------------------------------------------------------------------------
__global__ void __launch_bounds__(256) k_gh(const float* __restrict__ wg,
                                            const float* __restrict__ h) {
    int w = (blockIdx.x * 256 + threadIdx.x) >> 5;   // 0..511
    int lane = threadIdx.x & 31;
    const float4* wr = (const float4*)(wg + w * SEQ);
    const float4* hr = (const float4*)h;
    float p = 0.f;
    #pragma unroll
    for (int c = 0; c < 4; c++) {
        float4 a = wr[lane + 32 * c], b = hr[lane + 32 * c];
        p += a.x * b.x + a.y * b.y + a.z * b.z + a.w * b.w;
    }
    #pragma unroll
    for (int o = 16; o; o >>= 1) p += __shfl_down_sync(0xffffffffu, p, o);
    if (lane == 0) g_gh[w] = p;
}

// ---------------------------------------------------------------------------
// GEMM1 split-K12: g_spart[kc] = wv[:, kc*32:+32] @ v[kc*32:+32, :]
// 128x64 block tile, slab 32 staged once, 8x4 per thread (32 FFMA : 3 LDS.128).
// kc==0 adds bias g_gh[m] (read after gridsync — k_gh overlapped via PDL).
// Grid (6 n, 4 m, 12 kc) = 288 blocks.
// ---------------------------------------------------------------------------
__global__ void __launch_bounds__(256) k_gemm1(const float* __restrict__ wv,
                                               const float* __restrict__ v) {
    constexpr int KS = 32;
    __shared__ float As[KS][132];   // As[k][m], 132*4B row stride (16B aligned)
    __shared__ float Bs[KS][68];

    const int tx = threadIdx.x;
    const int tn = tx & 15;         // n group of 4
    const int tm = tx >> 4;         // m group of 8
    const int bn = blockIdx.x, bm = blockIdx.y, kc = blockIdx.z;
    const int kbase = kc * KS;

    // A tile: wv rows bm*128..+127, cols kbase..+31 -> transposed As[k][m]
    {
        int m = tx >> 1, c0 = (tx & 1) * 16;
        const float* ap = wv + (bm * 128 + m) * DD + kbase + c0;
        #pragma unroll
        for (int q = 0; q < 4; q++) {
            float4 a = *(const float4*)(ap + 4 * q);
            As[c0 + 4 * q + 0][m] = a.x; As[c0 + 4 * q + 1][m] = a.y;
            As[c0 + 4 * q + 2][m] = a.z; As[c0 + 4 * q + 3][m] = a.w;
        }
    }
    // B tile: v rows kbase..+31, cols bn*64..+63
    #pragma unroll
    for (int q = 0; q < 2; q++) {
        int e = tx + 256 * q;
        int k = e >> 4, n4 = (e & 15) * 4;
        *(float4*)&Bs[k][n4] = *(const float4*)&v[(kbase + k) * LL + bn * 64 + n4];
    }
    __syncthreads();

    float acc[8][4] = {};
    #pragma unroll 8
    for (int k = 0; k < KS; k++) {
        float4 a0 = *(const float4*)&As[k][tm * 8];
        float4 a1 = *(const float4*)&As[k][tm * 8 + 4];
        float4 b  = *(const float4*)&Bs[k][tn * 4];
        float av[8] = {a0.x, a0.y, a0.z, a0.w, a1.x, a1.y, a1.z, a1.w};
        float bv[4] = {b.x, b.y, b.z, b.w};
        #pragma unroll
        for (int i = 0; i < 8; i++)
            #pragma unroll
            for (int j = 0; j < 4; j++)
                acc[i][j] += av[i] * bv[j];
    }

    cudaGridDependencySynchronize();   // g_gh ready (k_gh overlapped)

    float* outp = g_spart[kc];
    #pragma unroll
    for (int i = 0; i < 8; i++) {
        int m = bm * 128 + tm * 8 + i;
        float bias = (kc == 0) ? g_gh[m] : 0.f;
        float4 r;
        r.x = acc[i][0] + bias; r.y = acc[i][1] + bias;
        r.z = acc[i][2] + bias; r.w = acc[i][3] + bias;
        *(float4*)&outp[m * LL + bn * 64 + tn * 4] = r;
    }
}

// ---------------------------------------------------------------------------
// GEMM2 split-K16: g_zpart[kc] = wh[:, kc*32:+32] @ tanh(s)[kc*32:+32, :]
// A (wh) staged BEFORE gridsync (overlaps GEMM1's tail); B = tanh(sum of 12
// s-partials) built on the fly. Grid (6 n, 3 m, 16 kc) = 288 blocks.
// ---------------------------------------------------------------------------
__global__ void __launch_bounds__(256) k_gemm2(const float* __restrict__ wh) {
    constexpr int KS = 32;
    __shared__ float As[KS][132];
    __shared__ float Bs[KS][68];

    const int tx = threadIdx.x;
    const int tn = tx & 15;
    const int tm = tx >> 4;
    const int bn = blockIdx.x, bm = blockIdx.y, kc = blockIdx.z;
    const int kbase = kc * KS;

    // A tile: wh rows bm*128..+127, cols kbase..+31 (independent of GEMM1)
    {
        int m = tx >> 1, c0 = (tx & 1) * 16;
        const float* ap = wh + (bm * 128 + m) * EMB + kbase + c0;
        #pragma unroll
        for (int q = 0; q < 4; q++) {
            float4 a = *(const float4*)(ap + 4 * q);
            As[c0 + 4 * q + 0][m] = a.x; As[c0 + 4 * q + 1][m] = a.y;
            As[c0 + 4 * q + 2][m] = a.z; As[c0 + 4 * q + 3][m] = a.w;
        }
    }

    cudaGridDependencySynchronize();   // s-partials ready

    // B tile: ts rows kbase..+31, cols bn*64..+63 = tanh(sum of NP1 partials)
    #pragma unroll
    for (int q = 0; q < 2; q++) {
        int e = tx + 256 * q;
        int k = e >> 4, n4 = (e & 15) * 4;
        int off = (kbase + k) * LL + bn * 64 + n4;
        float4 s = *(const float4*)&g_spart[0][off];
        #pragma unroll
        for (int p = 1; p < NP1; p++) {
            float4 t = *(const float4*)&g_spart[p][off];
            s.x += t.x; s.y += t.y; s.z += t.z; s.w += t.w;
        }
        float4 b;
        b.x = tanhf(s.x); b.y = tanhf(s.y); b.z = tanhf(s.z); b.w = tanhf(s.w);
        *(float4*)&Bs[k][n4] = b;
    }
    __syncthreads();

    float acc[8][4] = {};
    #pragma unroll 8
    for (int k = 0; k < KS; k++) {
        float4 a0 = *(const float4*)&As[k][tm * 8];
        float4 a1 = *(const float4*)&As[k][tm * 8 + 4];
        float4 b  = *(const float4*)&Bs[k][tn * 4];
        float av[8] = {a0.x, a0.y, a0.z, a0.w, a1.x, a1.y, a1.z, a1.w};
        float bv[4] = {b.x, b.y, b.z, b.w};
        #pragma unroll
        for (int i = 0; i < 8; i++)
            #pragma unroll
            for (int j = 0; j < 4; j++)
                acc[i][j] += av[i] * bv[j];
    }

    float* outp = g_zpart[kc];
    #pragma unroll
    for (int i = 0; i < 8; i++) {
        int m = bm * 128 + tm * 8 + i;
        float4 r;
        r.x = acc[i][0]; r.y = acc[i][1]; r.z = acc[i][2]; r.w = acc[i][3];
        *(float4*)&outp[m * LL + bn * 64 + tn * 4] = r;
    }
}

// ---------------------------------------------------------------------------
// Row softmax over z = sum of NP2 partials. One warp per row.
// ---------------------------------------------------------------------------
__global__ void k_softmax() {
    cudaGridDependencySynchronize();

    int warp = (blockIdx.x * blockDim.x + threadIdx.x) >> 5;   // 0..383
    int lane = threadIdx.x & 31;
    const int row = warp * LL;
    float4* ar = (float4*)(g_alpha + row);

    float4 x[3];
    #pragma unroll
    for (int c = 0; c < 3; c++) {
        int idx = (row >> 2) + lane + c * 32;
        float4 s = ((const float4*)g_zpart[0])[idx];
        #pragma unroll
        for (int p = 1; p < NP2; p++) {
            float4 t = ((const float4*)g_zpart[p])[idx];
            s.x += t.x; s.y += t.y; s.z += t.z; s.w += t.w;
        }
        x[c] = s;
    }

    float m = -1e30f;
    #pragma unroll
    for (int c = 0; c < 3; c++)
        m = fmaxf(m, fmaxf(fmaxf(x[c].x, x[c].y), fmaxf(x[c].z, x[c].w)));
    #pragma unroll
    for (int o = 16; o; o >>= 1) m = fmaxf(m, __shfl_xor_sync(0xffffffffu, m, o));

    float s = 0.f;
    #pragma unroll
    for (int c = 0; c < 3; c++) {
        x[c].x = __expf(x[c].x - m); x[c].y = __expf(x[c].y - m);
        x[c].z = __expf(x[c].z - m); x[c].w = __expf(x[c].w - m);
        s += (x[c].x + x[c].y) + (x[c].z + x[c].w);
    }
    #pragma unroll
    for (int o = 16; o; o >>= 1) s += __shfl_xor_sync(0xffffffffu, s, o);
    float inv = 1.f / s;

    #pragma unroll
    for (int c = 0; c < 3; c++) {
        x[c].x *= inv; x[c].y *= inv; x[c].z *= inv; x[c].w *= inv;
        ar[lane + c * 32] = x[c];
    }
}

// ---------------------------------------------------------------------------
// out[i,j,k] = v[j,k] * alpha[i,j].  v loads issued BEFORE gridsync (overlap
// with softmax tail). At write roofline — core loop unchanged.
// ---------------------------------------------------------------------------
__global__ void __launch_bounds__(384) k_out(const float* __restrict__ v,
                                             float4* __restrict__ out) {
    const int jb = blockIdx.x;    // 0..11   (32 j's each)
    const int ic = blockIdx.y;    // 0..23   (16 i's each)
    const int t  = threadIdx.x;   // 0..383

    const int g  = t / 96;        // 0..3
    const int k4 = t % 96;        // 0..95

    __shared__ float sa[16][32];

    float4 vv[8];
    #pragma unroll
    for (int jlo = 0; jlo < 8; jlo++)
        vv[jlo] = ((const float4*)v)[(jb * 32 + jlo * 4 + g) * 96 + k4];

    cudaGridDependencySynchronize();   // alpha ready

    #pragma unroll
    for (int idx = t; idx < 512; idx += 384) {
        int r = idx >> 5, c = idx & 31;
        sa[r][c] = g_alpha[(ic * 16 + r) * LL + jb * 32 + c];
    }
    __syncthreads();

    #pragma unroll 2
    for (int il = 0; il < 16; il++) {
        float4* o = out + ((size_t)(ic * 16 + il) * LL + jb * 32) * 96 + g * 96 + k4;
        #pragma unroll
        for (int jlo = 0; jlo < 8; jlo++) {
            float a = sa[il][jlo * 4 + g];
            float4 r;
            r.x = vv[jlo].x * a; r.y = vv[jlo].y * a;
            r.z = vv[jlo].z * a; r.w = vv[jlo].w * a;
            __stcs(o + jlo * 4 * 96, r);
        }
    }
}

// ---------------------------------------------------------------------------
template <typename F, typename... Args>
static void pdl_launch(F kern, dim3 g, dim3 b, Args... args) {
    cudaLaunchConfig_t cfg = {};
    cfg.gridDim = g; cfg.blockDim = b;
    cfg.dynamicSmemBytes = 0; cfg.stream = 0;
    cudaLaunchAttribute at;
    at.id = cudaLaunchAttributeProgrammaticStreamSerialization;
    at.val.programmaticStreamSerializationAllowed = 1;
    cfg.attrs = &at; cfg.numAttrs = 1;
    cudaLaunchKernelEx(&cfg, kern, args...);
}

extern "C" void kernel_launch(void* const* d_in, const int* in_sizes, int n_in,
                              void* d_out, int out_size) {
    const float* h  = (const float*)d_in[0];   // (512,1)
    const float* v  = (const float*)d_in[1];   // (384,384)
    const float* wh = (const float*)d_in[2];   // (384,512)
    const float* wv = (const float*)d_in[3];   // (512,384)
    const float* wg = (const float*)d_in[4];   // (512,512)

    k_gh<<<64, 256>>>(wg, h);

    pdl_launch(k_gemm1, dim3(LL / 64, EMB / 128, NP1), dim3(256), wv, v);
    pdl_launch(k_gemm2, dim3(LL / 64, LL / 128, NP2), dim3(256), wh);
    pdl_launch(k_softmax, dim3(96), dim3(128));
    pdl_launch(k_out, dim3(12, 24), dim3(384), v, (float4*)d_out);

    (void)in_sizes; (void)n_in; (void)out_size;
}

// round 8
// speedup vs baseline: 1.3286x; 1.0149x over previous
#include <cuda_runtime.h>
#include <math.h>

#define SEQ 512   // hidden dim of h
#define EMB 512   // embedding dim
#define DD  384   // vfeat channels
#define LL  384   // vfeat regions

#define NP1 12    // split-K partials for GEMM1 (K=384, slab 32)
#define NP2 16    // split-K partials for GEMM2 (K=512, slab 32)

// Scratch (device globals — no allocation allowed in kernel_launch)
__device__ float g_gh[EMB];               // wg @ h
__device__ float g_spart[NP1][EMB * LL];  // split-K partials of s = wv@v (+bias in part 0)
__device__ float g_zpart[NP2][LL * LL];   // split-K partials of z = wh@tanh(s)
__device__ float g_alpha[LL * LL];        // softmax rows (384,384)

// ---------------------------------------------------------------------------
// gh[row] = dot(wg[row,:], h). One warp per row; overlapped under GEMM1 (PDL).
// ---------------------------------------------------------------------------
__global__ void __launch_bounds__(256) k_gh(const float* __restrict__ wg,
                                            const float* __restrict__ h) {
    int w = (blockIdx.x * 256 + threadIdx.x) >> 5;   // 0..511
    int lane = threadIdx.x & 31;
    const float4* wr = (const float4*)(wg + w * SEQ);
    const float4* hr = (const float4*)h;
    float p = 0.f;
    #pragma unroll
    for (int c = 0; c < 4; c++) {
        float4 a = wr[lane + 32 * c], b = hr[lane + 32 * c];
        p += a.x * b.x + a.y * b.y + a.z * b.z + a.w * b.w;
    }
    #pragma unroll
    for (int o = 16; o; o >>= 1) p += __shfl_down_sync(0xffffffffu, p, o);
    if (lane == 0) g_gh[w] = p;
}

// ---------------------------------------------------------------------------
// GEMM1 split-K12: g_spart[kc] = wv[:, kc*32:+32] @ v[kc*32:+32, :]
// 128x64 block tile, slab 32 staged once, 8x4 per thread.
// kc==0 adds bias g_gh[m] (after gridsync). Grid (6,4,12) = 288 blocks.
// ---------------------------------------------------------------------------
__global__ void __launch_bounds__(256) k_gemm1(const float* __restrict__ wv,
                                               const float* __restrict__ v) {
    constexpr int KS = 32;
    __shared__ float As[KS][132];
    __shared__ float Bs[KS][68];

    const int tx = threadIdx.x;
    const int tn = tx & 15;
    const int tm = tx >> 4;
    const int bn = blockIdx.x, bm = blockIdx.y, kc = blockIdx.z;
    const int kbase = kc * KS;

    {
        int m = tx >> 1, c0 = (tx & 1) * 16;
        const float* ap = wv + (bm * 128 + m) * DD + kbase + c0;
        #pragma unroll
        for (int q = 0; q < 4; q++) {
            float4 a = *(const float4*)(ap + 4 * q);
            As[c0 + 4 * q + 0][m] = a.x; As[c0 + 4 * q + 1][m] = a.y;
            As[c0 + 4 * q + 2][m] = a.z; As[c0 + 4 * q + 3][m] = a.w;
        }
    }
    #pragma unroll
    for (int q = 0; q < 2; q++) {
        int e = tx + 256 * q;
        int k = e >> 4, n4 = (e & 15) * 4;
        *(float4*)&Bs[k][n4] = *(const float4*)&v[(kbase + k) * LL + bn * 64 + n4];
    }
    __syncthreads();

    float acc[8][4] = {};
    #pragma unroll 8
    for (int k = 0; k < KS; k++) {
        float4 a0 = *(const float4*)&As[k][tm * 8];
        float4 a1 = *(const float4*)&As[k][tm * 8 + 4];
        float4 b  = *(const float4*)&Bs[k][tn * 4];
        float av[8] = {a0.x, a0.y, a0.z, a0.w, a1.x, a1.y, a1.z, a1.w};
        float bv[4] = {b.x, b.y, b.z, b.w};
        #pragma unroll
        for (int i = 0; i < 8; i++)
            #pragma unroll
            for (int j = 0; j < 4; j++)
                acc[i][j] += av[i] * bv[j];
    }

    cudaGridDependencySynchronize();   // g_gh ready (k_gh overlapped)

    float* outp = g_spart[kc];
    #pragma unroll
    for (int i = 0; i < 8; i++) {
        int m = bm * 128 + tm * 8 + i;
        float bias = (kc == 0) ? g_gh[m] : 0.f;
        float4 r;
        r.x = acc[i][0] + bias; r.y = acc[i][1] + bias;
        r.z = acc[i][2] + bias; r.w = acc[i][3] + bias;
        *(float4*)&outp[m * LL + bn * 64 + tn * 4] = r;
    }
}

// ---------------------------------------------------------------------------
// GEMM2 split-K16: g_zpart[kc] = wh[:, kc*32:+32] @ tanh(s)[kc*32:+32, :]
// A (wh) staged BEFORE gridsync; B = tanh(sum of 12 s-partials) on the fly.
// Grid (6,3,16) = 288 blocks.
// ---------------------------------------------------------------------------
__global__ void __launch_bounds__(256) k_gemm2(const float* __restrict__ wh) {
    constexpr int KS = 32;
    __shared__ float As[KS][132];
    __shared__ float Bs[KS][68];

    const int tx = threadIdx.x;
    const int tn = tx & 15;
    const int tm = tx >> 4;
    const int bn = blockIdx.x, bm = blockIdx.y, kc = blockIdx.z;
    const int kbase = kc * KS;

    {
        int m = tx >> 1, c0 = (tx & 1) * 16;
        const float* ap = wh + (bm * 128 + m) * EMB + kbase + c0;
        #pragma unroll
        for (int q = 0; q < 4; q++) {
            float4 a = *(const float4*)(ap + 4 * q);
            As[c0 + 4 * q + 0][m] = a.x; As[c0 + 4 * q + 1][m] = a.y;
            As[c0 + 4 * q + 2][m] = a.z; As[c0 + 4 * q + 3][m] = a.w;
        }
    }

    cudaGridDependencySynchronize();   // s-partials ready

    #pragma unroll
    for (int q = 0; q < 2; q++) {
        int e = tx + 256 * q;
        int k = e >> 4, n4 = (e & 15) * 4;
        int off = (kbase + k) * LL + bn * 64 + n4;
        float4 s = *(const float4*)&g_spart[0][off];
        #pragma unroll
        for (int p = 1; p < NP1; p++) {
            float4 t = *(const float4*)&g_spart[p][off];
            s.x += t.x; s.y += t.y; s.z += t.z; s.w += t.w;
        }
        float4 b;
        b.x = tanhf(s.x); b.y = tanhf(s.y); b.z = tanhf(s.z); b.w = tanhf(s.w);
        *(float4*)&Bs[k][n4] = b;
    }
    __syncthreads();

    float acc[8][4] = {};
    #pragma unroll 8
    for (int k = 0; k < KS; k++) {
        float4 a0 = *(const float4*)&As[k][tm * 8];
        float4 a1 = *(const float4*)&As[k][tm * 8 + 4];
        float4 b  = *(const float4*)&Bs[k][tn * 4];
        float av[8] = {a0.x, a0.y, a0.z, a0.w, a1.x, a1.y, a1.z, a1.w};
        float bv[4] = {b.x, b.y, b.z, b.w};
        #pragma unroll
        for (int i = 0; i < 8; i++)
            #pragma unroll
            for (int j = 0; j < 4; j++)
                acc[i][j] += av[i] * bv[j];
    }

    float* outp = g_zpart[kc];
    #pragma unroll
    for (int i = 0; i < 8; i++) {
        int m = bm * 128 + tm * 8 + i;
        float4 r;
        r.x = acc[i][0]; r.y = acc[i][1]; r.z = acc[i][2]; r.w = acc[i][3];
        *(float4*)&outp[m * LL + bn * 64 + tn * 4] = r;
    }
}

// ---------------------------------------------------------------------------
// Row softmax over z = sum of NP2 partials.
// ONE BLOCK PER ROW (384 blocks x 128 threads). Thread t<96 owns float4
// column t: 16 independent partial loads in flight (MLP=16), then 2-level
// max/sum reduction (warp shuffle + 3-word smem). 4x the blocks, 3x the
// threads, 5x the MLP of the old warp-per-row version.
// ---------------------------------------------------------------------------
__global__ void __launch_bounds__(128) k_softmax() {
    cudaGridDependencySynchronize();

    const int row = blockIdx.x;            // 0..383
    const int t = threadIdx.x;             // 0..127 (96 active for data)
    const int lane = t & 31, w = t >> 5;

    __shared__ float sred[4];
    __shared__ float ssum[4];

    float4 x = make_float4(0.f, 0.f, 0.f, 0.f);
    const int idx = row * 96 + (t < 96 ? t : 95);
    {
        float4 s = ((const float4*)g_zpart[0])[idx];
        #pragma unroll
        for (int p = 1; p < NP2; p++) {
            float4 q = ((const float4*)g_zpart[p])[idx];
            s.x += q.x; s.y += q.y; s.z += q.z; s.w += q.w;
        }
        x = s;
    }

    // block max
    float m = fmaxf(fmaxf(x.x, x.y), fmaxf(x.z, x.w));
    if (t >= 96) m = -1e30f;
    #pragma unroll
    for (int o = 16; o; o >>= 1) m = fmaxf(m, __shfl_xor_sync(0xffffffffu, m, o));
    if (lane == 0) sred[w] = m;
    __syncthreads();
    m = fmaxf(fmaxf(sred[0], sred[1]), fmaxf(sred[2], sred[3]));

    // exp + block sum
    x.x = __expf(x.x - m); x.y = __expf(x.y - m);
    x.z = __expf(x.z - m); x.w = __expf(x.w - m);
    float s = (x.x + x.y) + (x.z + x.w);
    if (t >= 96) s = 0.f;
    #pragma unroll
    for (int o = 16; o; o >>= 1) s += __shfl_xor_sync(0xffffffffu, s, o);
    if (lane == 0) ssum[w] = s;
    __syncthreads();
    float inv = 1.f / (((ssum[0] + ssum[1]) + (ssum[2] + ssum[3])));

    if (t < 96) {
        x.x *= inv; x.y *= inv; x.z *= inv; x.w *= inv;
        ((float4*)g_alpha)[idx] = x;
    }
}

// ---------------------------------------------------------------------------
// out[i,j,k] = v[j,k] * alpha[i,j].  v loads issued BEFORE gridsync.
// At write roofline — unchanged.
// ---------------------------------------------------------------------------
__global__ void __launch_bounds__(384) k_out(const float* __restrict__ v,
                                             float4* __restrict__ out) {
    const int jb = blockIdx.x;    // 0..11
    const int ic = blockIdx.y;    // 0..23
    const int t  = threadIdx.x;   // 0..383

    const int g  = t / 96;
    const int k4 = t % 96;

    __shared__ float sa[16][32];

    float4 vv[8];
    #pragma unroll
    for (int jlo = 0; jlo < 8; jlo++)
        vv[jlo] = ((const float4*)v)[(jb * 32 + jlo * 4 + g) * 96 + k4];

    cudaGridDependencySynchronize();   // alpha ready

    #pragma unroll
    for (int idx = t; idx < 512; idx += 384) {
        int r = idx >> 5, c = idx & 31;
        sa[r][c] = g_alpha[(ic * 16 + r) * LL + jb * 32 + c];
    }
    __syncthreads();

    #pragma unroll 2
    for (int il = 0; il < 16; il++) {
        float4* o = out + ((size_t)(ic * 16 + il) * LL + jb * 32) * 96 + g * 96 + k4;
        #pragma unroll
        for (int jlo = 0; jlo < 8; jlo++) {
            float a = sa[il][jlo * 4 + g];
            float4 r;
            r.x = vv[jlo].x * a; r.y = vv[jlo].y * a;
            r.z = vv[jlo].z * a; r.w = vv[jlo].w * a;
            __stcs(o + jlo * 4 * 96, r);
        }
    }
}

// ---------------------------------------------------------------------------
template <typename F, typename... Args>
static void pdl_launch(F kern, dim3 g, dim3 b, Args... args) {
    cudaLaunchConfig_t cfg = {};
    cfg.gridDim = g; cfg.blockDim = b;
    cfg.dynamicSmemBytes = 0; cfg.stream = 0;
    cudaLaunchAttribute at;
    at.id = cudaLaunchAttributeProgrammaticStreamSerialization;
    at.val.programmaticStreamSerializationAllowed = 1;
    cfg.attrs = &at; cfg.numAttrs = 1;
    cudaLaunchKernelEx(&cfg, kern, args...);
}

extern "C" void kernel_launch(void* const* d_in, const int* in_sizes, int n_in,
                              void* d_out, int out_size) {
    const float* h  = (const float*)d_in[0];   // (512,1)
    const float* v  = (const float*)d_in[1];   // (384,384)
    const float* wh = (const float*)d_in[2];   // (384,512)
    const float* wv = (const float*)d_in[3];   // (512,384)
    const float* wg = (const float*)d_in[4];   // (512,512)

    k_gh<<<64, 256>>>(wg, h);

    pdl_launch(k_gemm1, dim3(LL / 64, EMB / 128, NP1), dim3(256), wv, v);
    pdl_launch(k_gemm2, dim3(LL / 64, LL / 128, NP2), dim3(256), wh);
    pdl_launch(k_softmax, dim3(LL), dim3(128));
    pdl_launch(k_out, dim3(12, 24), dim3(384), v, (float4*)d_out);

    (void)in_sizes; (void)n_in; (void)out_size;
}

// round 9
// speedup vs baseline: 1.3424x; 1.0104x over previous
#include <cuda_runtime.h>
#include <math.h>

#define SEQ 512   // hidden dim of h
#define EMB 512   // embedding dim
#define DD  384   // vfeat channels
#define LL  384   // vfeat regions

#define NP1 6     // split-K partials for GEMM1 (K=384, slab 64)
#define NP2 8     // split-K partials for GEMM2 (K=512, slab 64)

// Scratch (device globals — no allocation allowed in kernel_launch)
__device__ float g_gh[EMB];               // wg @ h
__device__ float g_spart[NP1][EMB * LL];  // split-K partials of s = wv@v (+bias in part 0)
__device__ float g_zpart[NP2][LL * LL];   // split-K partials of z = wh@tanh(s)
__device__ float g_alpha[LL * LL];        // softmax rows (384,384)

// ---------------------------------------------------------------------------
// gh[row] = dot(wg[row,:], h). One warp per row; overlapped under GEMM1 (PDL).
// ---------------------------------------------------------------------------
__global__ void __launch_bounds__(256) k_gh(const float* __restrict__ wg,
                                            const float* __restrict__ h) {
    int w = (blockIdx.x * 256 + threadIdx.x) >> 5;   // 0..511
    int lane = threadIdx.x & 31;
    const float4* wr = (const float4*)(wg + w * SEQ);
    const float4* hr = (const float4*)h;
    float p = 0.f;
    #pragma unroll
    for (int c = 0; c < 4; c++) {
        float4 a = wr[lane + 32 * c], b = hr[lane + 32 * c];
        p += a.x * b.x + a.y * b.y + a.z * b.z + a.w * b.w;
    }
    #pragma unroll
    for (int o = 16; o; o >>= 1) p += __shfl_down_sync(0xffffffffu, p, o);
    if (lane == 0) g_gh[w] = p;
}

// ---------------------------------------------------------------------------
// GEMM1 split-K6: g_spart[kc] = wv[:, kc*64:+64] @ v[kc*64:+64, :]
// 128x64 block tile, 64-deep slab staged once, 8x4 per thread.
// kc==0 adds bias g_gh[m] (after gridsync). Grid (6,4,6) = 144 blocks (1/SM).
// ---------------------------------------------------------------------------
__global__ void __launch_bounds__(256) k_gemm1(const float* __restrict__ wv,
                                               const float* __restrict__ v) {
    constexpr int KS = 64;
    __shared__ float As[KS][132];   // As[k][m]
    __shared__ float Bs[KS][68];

    const int tx = threadIdx.x;
    const int tn = tx & 15;
    const int tm = tx >> 4;
    const int bn = blockIdx.x, bm = blockIdx.y, kc = blockIdx.z;
    const int kbase = kc * KS;

    // A tile: wv rows bm*128..+127, cols kbase..+63 -> transposed As[k][m]
    {
        int m = tx >> 1, c0 = (tx & 1) * 32;
        const float* ap = wv + (bm * 128 + m) * DD + kbase + c0;
        #pragma unroll
        for (int q = 0; q < 8; q++) {
            float4 a = *(const float4*)(ap + 4 * q);
            As[c0 + 4 * q + 0][m] = a.x; As[c0 + 4 * q + 1][m] = a.y;
            As[c0 + 4 * q + 2][m] = a.z; As[c0 + 4 * q + 3][m] = a.w;
        }
    }
    // B tile: v rows kbase..+63, cols bn*64..+63
    #pragma unroll
    for (int q = 0; q < 4; q++) {
        int e = tx + 256 * q;
        int k = e >> 4, n4 = (e & 15) * 4;
        *(float4*)&Bs[k][n4] = *(const float4*)&v[(kbase + k) * LL + bn * 64 + n4];
    }
    __syncthreads();

    float acc[8][4] = {};
    #pragma unroll 8
    for (int k = 0; k < KS; k++) {
        float4 a0 = *(const float4*)&As[k][tm * 8];
        float4 a1 = *(const float4*)&As[k][tm * 8 + 4];
        float4 b  = *(const float4*)&Bs[k][tn * 4];
        float av[8] = {a0.x, a0.y, a0.z, a0.w, a1.x, a1.y, a1.z, a1.w};
        float bv[4] = {b.x, b.y, b.z, b.w};
        #pragma unroll
        for (int i = 0; i < 8; i++)
            #pragma unroll
            for (int j = 0; j < 4; j++)
                acc[i][j] += av[i] * bv[j];
    }

    cudaGridDependencySynchronize();   // g_gh ready (k_gh overlapped)

    float* outp = g_spart[kc];
    #pragma unroll
    for (int i = 0; i < 8; i++) {
        int m = bm * 128 + tm * 8 + i;
        float bias = (kc == 0) ? g_gh[m] : 0.f;
        float4 r;
        r.x = acc[i][0] + bias; r.y = acc[i][1] + bias;
        r.z = acc[i][2] + bias; r.w = acc[i][3] + bias;
        *(float4*)&outp[m * LL + bn * 64 + tn * 4] = r;
    }
}

// ---------------------------------------------------------------------------
// GEMM2 split-K8: g_zpart[kc] = wh[:, kc*64:+64] @ tanh(s)[kc*64:+64, :]
// A (wh) staged BEFORE gridsync; B = tanh(sum of 6 s-partials) on the fly.
// Grid (6,3,8) = 144 blocks.
// ---------------------------------------------------------------------------
__global__ void __launch_bounds__(256) k_gemm2(const float* __restrict__ wh) {
    constexpr int KS = 64;
    __shared__ float As[KS][132];
    __shared__ float Bs[KS][68];

    const int tx = threadIdx.x;
    const int tn = tx & 15;
    const int tm = tx >> 4;
    const int bn = blockIdx.x, bm = blockIdx.y, kc = blockIdx.z;
    const int kbase = kc * KS;

    // A tile: wh rows bm*128..+127, cols kbase..+63 (independent of GEMM1)
    {
        int m = tx >> 1, c0 = (tx & 1) * 32;
        const float* ap = wh + (bm * 128 + m) * EMB + kbase + c0;
        #pragma unroll
        for (int q = 0; q < 8; q++) {
            float4 a = *(const float4*)(ap + 4 * q);
            As[c0 + 4 * q + 0][m] = a.x; As[c0 + 4 * q + 1][m] = a.y;
            As[c0 + 4 * q + 2][m] = a.z; As[c0 + 4 * q + 3][m] = a.w;
        }
    }

    cudaGridDependencySynchronize();   // s-partials ready

    // B tile: ts rows kbase..+63, cols bn*64..+63 = tanh(sum of NP1 partials)
    #pragma unroll
    for (int q = 0; q < 4; q++) {
        int e = tx + 256 * q;
        int k = e >> 4, n4 = (e & 15) * 4;
        int off = (kbase + k) * LL + bn * 64 + n4;
        float4 s = *(const float4*)&g_spart[0][off];
        #pragma unroll
        for (int p = 1; p < NP1; p++) {
            float4 t = *(const float4*)&g_spart[p][off];
            s.x += t.x; s.y += t.y; s.z += t.z; s.w += t.w;
        }
        float4 b;
        b.x = tanhf(s.x); b.y = tanhf(s.y); b.z = tanhf(s.z); b.w = tanhf(s.w);
        *(float4*)&Bs[k][n4] = b;
    }
    __syncthreads();

    float acc[8][4] = {};
    #pragma unroll 8
    for (int k = 0; k < KS; k++) {
        float4 a0 = *(const float4*)&As[k][tm * 8];
        float4 a1 = *(const float4*)&As[k][tm * 8 + 4];
        float4 b  = *(const float4*)&Bs[k][tn * 4];
        float av[8] = {a0.x, a0.y, a0.z, a0.w, a1.x, a1.y, a1.z, a1.w};
        float bv[4] = {b.x, b.y, b.z, b.w};
        #pragma unroll
        for (int i = 0; i < 8; i++)
            #pragma unroll
            for (int j = 0; j < 4; j++)
                acc[i][j] += av[i] * bv[j];
    }

    float* outp = g_zpart[kc];
    #pragma unroll
    for (int i = 0; i < 8; i++) {
        int m = bm * 128 + tm * 8 + i;
        float4 r;
        r.x = acc[i][0]; r.y = acc[i][1]; r.z = acc[i][2]; r.w = acc[i][3];
        *(float4*)&outp[m * LL + bn * 64 + tn * 4] = r;
    }
}

// ---------------------------------------------------------------------------
// Row softmax over z = sum of NP2 partials. One block per row,
// 128 threads (96 active), MLP=NP2 independent partial loads.
// ---------------------------------------------------------------------------
__global__ void __launch_bounds__(128) k_softmax() {
    cudaGridDependencySynchronize();

    const int row = blockIdx.x;            // 0..383
    const int t = threadIdx.x;             // 0..127 (96 active for data)
    const int lane = t & 31, w = t >> 5;

    __shared__ float sred[4];
    __shared__ float ssum[4];

    float4 x;
    const int idx = row * 96 + (t < 96 ? t : 95);
    {
        float4 s = ((const float4*)g_zpart[0])[idx];
        #pragma unroll
        for (int p = 1; p < NP2; p++) {
            float4 q = ((const float4*)g_zpart[p])[idx];
            s.x += q.x; s.y += q.y; s.z += q.z; s.w += q.w;
        }
        x = s;
    }

    float m = fmaxf(fmaxf(x.x, x.y), fmaxf(x.z, x.w));
    if (t >= 96) m = -1e30f;
    #pragma unroll
    for (int o = 16; o; o >>= 1) m = fmaxf(m, __shfl_xor_sync(0xffffffffu, m, o));
    if (lane == 0) sred[w] = m;
    __syncthreads();
    m = fmaxf(fmaxf(sred[0], sred[1]), fmaxf(sred[2], sred[3]));

    x.x = __expf(x.x - m); x.y = __expf(x.y - m);
    x.z = __expf(x.z - m); x.w = __expf(x.w - m);
    float s = (x.x + x.y) + (x.z + x.w);
    if (t >= 96) s = 0.f;
    #pragma unroll
    for (int o = 16; o; o >>= 1) s += __shfl_xor_sync(0xffffffffu, s, o);
    if (lane == 0) ssum[w] = s;
    __syncthreads();
    float inv = 1.f / (((ssum[0] + ssum[1]) + (ssum[2] + ssum[3])));

    if (t < 96) {
        x.x *= inv; x.y *= inv; x.z *= inv; x.w *= inv;
        ((float4*)g_alpha)[idx] = x;
    }
}

// ---------------------------------------------------------------------------
// out[i,j,k] = v[j,k] * alpha[i,j].  v loads issued BEFORE gridsync.
// At write roofline — unchanged.
// ---------------------------------------------------------------------------
__global__ void __launch_bounds__(384) k_out(const float* __restrict__ v,
                                             float4* __restrict__ out) {
    const int jb = blockIdx.x;    // 0..11
    const int ic = blockIdx.y;    // 0..23
    const int t  = threadIdx.x;   // 0..383

    const int g  = t / 96;
    const int k4 = t % 96;

    __shared__ float sa[16][32];

    float4 vv[8];
    #pragma unroll
    for (int jlo = 0; jlo < 8; jlo++)
        vv[jlo] = ((const float4*)v)[(jb * 32 + jlo * 4 + g) * 96 + k4];

    cudaGridDependencySynchronize();   // alpha ready

    #pragma unroll
    for (int idx = t; idx < 512; idx += 384) {
        int r = idx >> 5, c = idx & 31;
        sa[r][c] = g_alpha[(ic * 16 + r) * LL + jb * 32 + c];
    }
    __syncthreads();

    #pragma unroll 2
    for (int il = 0; il < 16; il++) {
        float4* o = out + ((size_t)(ic * 16 + il) * LL + jb * 32) * 96 + g * 96 + k4;
        #pragma unroll
        for (int jlo = 0; jlo < 8; jlo++) {
            float a = sa[il][jlo * 4 + g];
            float4 r;
            r.x = vv[jlo].x * a; r.y = vv[jlo].y * a;
            r.z = vv[jlo].z * a; r.w = vv[jlo].w * a;
            __stcs(o + jlo * 4 * 96, r);
        }
    }
}

// ---------------------------------------------------------------------------
template <typename F, typename... Args>
static void pdl_launch(F kern, dim3 g, dim3 b, Args... args) {
    cudaLaunchConfig_t cfg = {};
    cfg.gridDim = g; cfg.blockDim = b;
    cfg.dynamicSmemBytes = 0; cfg.stream = 0;
    cudaLaunchAttribute at;
    at.id = cudaLaunchAttributeProgrammaticStreamSerialization;
    at.val.programmaticStreamSerializationAllowed = 1;
    cfg.attrs = &at; cfg.numAttrs = 1;
    cudaLaunchKernelEx(&cfg, kern, args...);
}

extern "C" void kernel_launch(void* const* d_in, const int* in_sizes, int n_in,
                              void* d_out, int out_size) {
    const float* h  = (const float*)d_in[0];   // (512,1)
    const float* v  = (const float*)d_in[1];   // (384,384)
    const float* wh = (const float*)d_in[2];   // (384,512)
    const float* wv = (const float*)d_in[3];   // (512,384)
    const float* wg = (const float*)d_in[4];   // (512,512)

    k_gh<<<64, 256>>>(wg, h);

    pdl_launch(k_gemm1, dim3(LL / 64, EMB / 128, NP1), dim3(256), wv, v);
    pdl_launch(k_gemm2, dim3(LL / 64, LL / 128, NP2), dim3(256), wh);
    pdl_launch(k_softmax, dim3(LL), dim3(128));
    pdl_launch(k_out, dim3(12, 24), dim3(384), v, (float4*)d_out);

    (void)in_sizes; (void)n_in; (void)out_size;
}